// round 7
// baseline (speedup 1.0000x reference)
#include <cuda_runtime.h>

#define NPTS 16384
#define KNN  16
#define CIMG 54
#define NCH  58                      // 54 img + dist + nb0..2
#define CSTRIDE (NPTS * KNN)
#define THREADS 256
#define WARPS 8
#define NB 32
#define NBLOCKS ((4 * NPTS) / NB)    // 2048

// ---------------- folded-weight scratch (device global; no allocs) ----------
struct Prep {
    float  ws[NCH * 32];     // [row c][o]: conv1 weight, BN-folded
    float2 w2c[32 * 32];     // [i][o2] = (w2_max, w2_mean/16), BN-folded
    float4 wep4[32];         // per o: (wep0, wep1, wep2, bias1_folded)
    float4 w2e4[32];         // per o2: (w2ep0, w2ep1, w2ep2, bias2_folded)
};
__device__ Prep g_prep;

// ---------------- packed fp32x2 helpers -------------------------------------
union F2U { float2 f; unsigned long long u; };
__device__ __forceinline__ float2 ffma2(float2 a, float2 b, float2 c) {
    F2U A, B, C, D;
    A.f = a; B.f = b; C.f = c;
    asm("fma.rn.f32x2 %0, %1, %2, %3;" : "=l"(D.u) : "l"(A.u), "l"(B.u), "l"(C.u));
    return D.f;
}
__device__ __forceinline__ float2 dup2(float w) {
    F2U D;
    asm("mov.b64 %0, {%1, %1};" : "=l"(D.u) : "f"(w));
    return D.f;
}

// ---------------- prep: fold BN + concat algebra into weights ---------------
__global__ void prep_kernel(
    const float* __restrict__ w1, const float* __restrict__ b1,
    const float* __restrict__ g1, const float* __restrict__ be1,
    const float* __restrict__ m1, const float* __restrict__ v1,
    const float* __restrict__ w2, const float* __restrict__ b2,
    const float* __restrict__ g2, const float* __restrict__ be2,
    const float* __restrict__ m2, const float* __restrict__ v2)
{
    __shared__ float s1[32], s2[32], bf1[32], bf2[32];
    int t = threadIdx.x;
    if (t < 32) {
        float sc = g1[t] / sqrtf(v1[t] + 1e-6f);
        s1[t]  = sc;
        bf1[t] = (b1[t] - m1[t]) * sc + be1[t];
        float sc2 = g2[t] / sqrtf(v2[t] + 1e-6f);
        s2[t]  = sc2;
        bf2[t] = (b2[t] - m2[t]) * sc2 + be2[t];
    }
    __syncthreads();

    // conv1 rows: 0..53 img (w1 col 10+c), 54 dist (col 9), 55..57 nb (col 3+c - col 6+c)
    for (int i = t; i < NCH * 32; i += blockDim.x) {
        int c = i >> 5, o = i & 31;
        float wv;
        if (c < 54)       wv = w1[o * 64 + 10 + c];
        else if (c == 54) wv = w1[o * 64 + 9];
        else              wv = w1[o * 64 + 3 + (c - 55)] - w1[o * 64 + 6 + (c - 55)];
        g_prep.ws[i] = wv * s1[o];
    }
    for (int i = t; i < 32 * 32; i += blockDim.x) {
        int c = i >> 5, o = i & 31;
        float wm = w2[o * 70 + c] * s2[o];
        float wsn = w2[o * 70 + 35 + c] * s2[o] * 0.0625f;
        g_prep.w2c[i] = make_float2(wm, wsn);
    }
    if (t < 32) {
        int o = t;
        g_prep.wep4[o] = make_float4(
            (w1[o * 64 + 0] + w1[o * 64 + 6]) * s1[o],
            (w1[o * 64 + 1] + w1[o * 64 + 7]) * s1[o],
            (w1[o * 64 + 2] + w1[o * 64 + 8]) * s1[o],
            bf1[o]);
        g_prep.w2e4[o] = make_float4(
            (w2[o * 70 + 32] + w2[o * 70 + 67]) * s2[o],
            (w2[o * 70 + 33] + w2[o * 70 + 68]) * s2[o],
            (w2[o * 70 + 34] + w2[o * 70 + 69]) * s2[o],
            bf2[o]);
    }
}

// ---------------- dynamic smem layout (floats) ------------------------------
// [0, 14848)        x-stage: [WARPS][2 buf][58 rows][16]
// [14848, 16896)    w2c (2048 floats)
// [16896, 17952)    out:  [32][33]
#define XSTRIDE (NCH * KNN)          // 928 floats per buffer
#define SMEM_FLOATS 17952
#define SMEM_BYTES  (SMEM_FLOATS * 4)

struct Ep { float e0, e1, e2; };

__global__ __launch_bounds__(THREADS, 2) void pif_main(
    const float* __restrict__ points, const float* __restrict__ img,
    const float* __restrict__ dist,   const int*   __restrict__ idx,
    float* __restrict__ out)
{
    extern __shared__ float smem[];
    float*  s_x    = smem;
    float2* s_w2c  = (float2*)(smem + 14848);
    float*  s_out  = smem + 16896;

    const int t    = threadIdx.x;
    const int lane = t & 31, wrp = t >> 5;

    // copy w2c to smem (bulk float4)
    {
        const float4* src = (const float4*)g_prep.w2c;
        float4* dst = (float4*)(smem + 14848);
        for (int i = t; i < 512; i += THREADS) dst[i] = src[i];
    }
    // conv1 weights -> registers (lane = out channel o)
    float wreg[NCH];
#pragma unroll
    for (int c = 0; c < NCH; c++) wreg[c] = g_prep.ws[c * 32 + lane];
    const float4 wep = g_prep.wep4[lane];
    const float4 w2e = g_prep.w2e4[lane];

    const int b  = blockIdx.x >> 9;
    const int n0 = (blockIdx.x & 511) * NB;
    const float* pts_b = points + b * (NPTS * 3);
    const float* img_b = img  + (size_t)b * (CIMG * (size_t)CSTRIDE);
    const float* dst_b = dist + b * (NPTS * KNN);
    const int*   idx_b = idx  + b * (NPTS * KNN);
    float*       out_b = out  + b * (32 * NPTS);

    float* my_x = s_x + wrp * (2 * XSTRIDE);

    // ---- cp.async prefetch: 55 rows (54 img + dist) x 64B ------------------
    auto prefetch = [&](int n, int bufsel) {
        float* db = my_x + bufsel * XSTRIDE;
        int q = lane;
#pragma unroll
        for (int w = 0; w < 7; w++) {
            if (q < 55 * 4) {
                int c = q >> 2, j = q & 3;
                const float* s = (c < CIMG)
                    ? img_b + (size_t)c * CSTRIDE + n * KNN + j * 4
                    : dst_b + n * KNN + j * 4;
                unsigned da = (unsigned)__cvta_generic_to_shared(db + c * KNN + j * 4);
                asm volatile("cp.async.cg.shared.global [%0], [%1], 16;"
                             :: "r"(da), "l"(s));
            }
            q += 32;
        }
        asm volatile("cp.async.commit_group;");
    };

    // ---- nb gather: lanes 0..15 fetch neighbor xyz, STS rows 55..57 --------
    auto gather_nb = [&](int n, int bufsel) {
        if (lane < 16) {
            int j = idx_b[n * KNN + lane];
            float p0 = pts_b[j * 3 + 0];
            float p1 = pts_b[j * 3 + 1];
            float p2 = pts_b[j * 3 + 2];
            float* r = my_x + bufsel * XSTRIDE + 55 * KNN + lane;
            r[0]  = p0;
            r[16] = p1;
            r[32] = p2;
        }
    };
    auto load_ep = [&](int n, Ep& e) {
        e.e0 = pts_b[n * 3 + 0];
        e.e1 = pts_b[n * 3 + 1];
        e.e2 = pts_b[n * 3 + 2];
    };

    const int nw = n0 + wrp * 4;
    Ep epc, epn;
    prefetch(nw, 0);
    gather_nb(nw, 0);
    load_ep(nw, epc);
    __syncthreads();                 // w2c visible

    float2 hreg[4];                  // pooled (max, sum) per unit, lane = o
    float  e2v[4];                   // conv2 ep-term per unit, lane = o2

#pragma unroll
    for (int it = 0; it < 4; ++it) {
        const int buf = it & 1;
        if (it < 3) {
            prefetch(nw + it + 1, buf ^ 1);
            gather_nb(nw + it + 1, buf ^ 1);
            load_ep(nw + it + 1, epn);
        }
        if (it < 3) asm volatile("cp.async.wait_group 1;");
        else        asm volatile("cp.async.wait_group 0;");
        __syncwarp();

        // conv2 ep-term for this unit (used later)
        e2v[it] = fmaf(w2e.x, epc.e0,
                  fmaf(w2e.y, epc.e1,
                  fmaf(w2e.z, epc.e2, w2e.w)));

        // acc[r] covers k=2r,2r+1 for this lane's out-channel; ep-term init
        const float e = fmaf(wep.x, epc.e0,
                        fmaf(wep.y, epc.e1,
                        fmaf(wep.z, epc.e2, wep.w)));
        float2 acc[8];
#pragma unroll
        for (int r = 0; r < 8; r++) acc[r] = make_float2(e, e);

        const float* xr = my_x + buf * XSTRIDE;
#pragma unroll
        for (int c = 0; c < NCH; c++) {
            const float2 wd = dup2(wreg[c]);
            const float4* xp = reinterpret_cast<const float4*>(xr + c * KNN);
            float4 x0 = xp[0], x1 = xp[1], x2 = xp[2], x3 = xp[3];
            acc[0] = ffma2(wd, make_float2(x0.x, x0.y), acc[0]);
            acc[1] = ffma2(wd, make_float2(x0.z, x0.w), acc[1]);
            acc[2] = ffma2(wd, make_float2(x1.x, x1.y), acc[2]);
            acc[3] = ffma2(wd, make_float2(x1.z, x1.w), acc[3]);
            acc[4] = ffma2(wd, make_float2(x2.x, x2.y), acc[4]);
            acc[5] = ffma2(wd, make_float2(x2.z, x2.w), acc[5]);
            acc[6] = ffma2(wd, make_float2(x3.x, x3.y), acc[6]);
            acc[7] = ffma2(wd, make_float2(x3.z, x3.w), acc[7]);
        }

        // ReLU + in-register pool over 16 k values; result stays in registers
        float2 mx = make_float2(fmaxf(acc[0].x, 0.f), fmaxf(acc[0].y, 0.f));
        float2 sm = mx;
#pragma unroll
        for (int r = 1; r < 8; r++) {
            float ax = fmaxf(acc[r].x, 0.f), ay = fmaxf(acc[r].y, 0.f);
            mx.x = fmaxf(mx.x, ax); mx.y = fmaxf(mx.y, ay);
            sm.x += ax;             sm.y += ay;
        }
        hreg[it] = make_float2(fmaxf(mx.x, mx.y), sm.x + sm.y);

        epc = epn;
    }

    // ---- conv2 for all 4 units: w2c read ONCE per warp, h via shfl ---------
    {
        float2 a0 = make_float2(e2v[0], 0.f);
        float2 a1 = make_float2(e2v[1], 0.f);
        float2 a2 = make_float2(e2v[2], 0.f);
        float2 a3 = make_float2(e2v[3], 0.f);
#pragma unroll 8
        for (int i = 0; i < 32; i++) {
            float2 w = s_w2c[i * 32 + lane];
            float2 h0 = make_float2(__shfl_sync(0xffffffffu, hreg[0].x, i),
                                    __shfl_sync(0xffffffffu, hreg[0].y, i));
            float2 h1 = make_float2(__shfl_sync(0xffffffffu, hreg[1].x, i),
                                    __shfl_sync(0xffffffffu, hreg[1].y, i));
            float2 h2 = make_float2(__shfl_sync(0xffffffffu, hreg[2].x, i),
                                    __shfl_sync(0xffffffffu, hreg[2].y, i));
            float2 h3 = make_float2(__shfl_sync(0xffffffffu, hreg[3].x, i),
                                    __shfl_sync(0xffffffffu, hreg[3].y, i));
            a0 = ffma2(w, h0, a0);
            a1 = ffma2(w, h1, a1);
            a2 = ffma2(w, h2, a2);
            a3 = ffma2(w, h3, a3);
        }
        float* so = s_out + lane * 33 + wrp * 4;
        so[0] = fmaxf(a0.x + a0.y, 0.0f);
        so[1] = fmaxf(a1.x + a1.y, 0.0f);
        so[2] = fmaxf(a2.x + a2.y, 0.0f);
        so[3] = fmaxf(a3.x + a3.y, 0.0f);
    }

    // block-wide sync, then fully coalesced float4 stores
    __syncthreads();
    {
        int o = t >> 3, c4 = (t & 7) * 4;
        float4 v = make_float4(s_out[o * 33 + c4],     s_out[o * 33 + c4 + 1],
                               s_out[o * 33 + c4 + 2], s_out[o * 33 + c4 + 3]);
        *reinterpret_cast<float4*>(out_b + o * NPTS + n0 + c4) = v;
    }
}

// ---------------- launch ----------------------------------------------------
extern "C" void kernel_launch(void* const* d_in, const int* in_sizes, int n_in,
                              void* d_out, int out_size)
{
    const float* points = (const float*)d_in[0];
    const float* img    = (const float*)d_in[1];
    const float* dist   = (const float*)d_in[2];
    const int*   idx    = (const int*)  d_in[3];

    prep_kernel<<<1, 256>>>(
        (const float*)d_in[4],  (const float*)d_in[5],
        (const float*)d_in[6],  (const float*)d_in[7],
        (const float*)d_in[8],  (const float*)d_in[9],
        (const float*)d_in[10], (const float*)d_in[11],
        (const float*)d_in[12], (const float*)d_in[13],
        (const float*)d_in[14], (const float*)d_in[15]);

    cudaFuncSetAttribute(pif_main, cudaFuncAttributeMaxDynamicSharedMemorySize,
                         SMEM_BYTES);
    pif_main<<<NBLOCKS, THREADS, SMEM_BYTES>>>(points, img, dist, idx,
                                               (float*)d_out);
}

// round 8
// speedup vs baseline: 1.0559x; 1.0559x over previous
#include <cuda_runtime.h>
#include <cuda.h>

#define NPTS 16384
#define KNN  16
#define CIMG 54
#define NCH  58                      // 54 img + dist + nb0..2
#define CSTRIDE (NPTS * KNN)
#define THREADS 256
#define WARPS 8
#define UPW 2                        // n-units per warp
#define NB (WARPS * UPW)             // 16 units per block
#define NBLOCKS ((4 * NPTS) / NB)    // 4096

// ---------------- folded-weight scratch (device global; no allocs) ----------
struct Prep {
    float  ws[NCH * 32];     // [row c][o]: conv1 weight, BN-folded
    float2 w2c[32 * 32];     // [i][o2] = (w2_max, w2_mean/16), BN-folded
    float4 wep4[32];         // per o: (wep0, wep1, wep2, bias1_folded)
    float4 w2e4[32];         // per o2: (w2ep0, w2ep1, w2ep2, bias2_folded)
};
__device__ Prep g_prep;

// ---------------- packed fp32x2 helpers -------------------------------------
union F2U { float2 f; unsigned long long u; };
__device__ __forceinline__ float2 ffma2(float2 a, float2 b, float2 c) {
    F2U A, B, C, D;
    A.f = a; B.f = b; C.f = c;
    asm("fma.rn.f32x2 %0, %1, %2, %3;" : "=l"(D.u) : "l"(A.u), "l"(B.u), "l"(C.u));
    return D.f;
}
__device__ __forceinline__ float2 dup2(float w) {
    F2U D;
    asm("mov.b64 %0, {%1, %1};" : "=l"(D.u) : "f"(w));
    return D.f;
}

// ---------------- prep: fold BN + concat algebra into weights ---------------
__global__ void prep_kernel(
    const float* __restrict__ w1, const float* __restrict__ b1,
    const float* __restrict__ g1, const float* __restrict__ be1,
    const float* __restrict__ m1, const float* __restrict__ v1,
    const float* __restrict__ w2, const float* __restrict__ b2,
    const float* __restrict__ g2, const float* __restrict__ be2,
    const float* __restrict__ m2, const float* __restrict__ v2)
{
    __shared__ float s1[32], s2[32], bf1[32], bf2[32];
    int t = threadIdx.x;
    if (t < 32) {
        float sc = g1[t] / sqrtf(v1[t] + 1e-6f);
        s1[t]  = sc;
        bf1[t] = (b1[t] - m1[t]) * sc + be1[t];
        float sc2 = g2[t] / sqrtf(v2[t] + 1e-6f);
        s2[t]  = sc2;
        bf2[t] = (b2[t] - m2[t]) * sc2 + be2[t];
    }
    __syncthreads();

    // conv1 rows: 0..53 img (w1 col 10+c), 54 dist (col 9), 55..57 nb (col 3+c - col 6+c)
    for (int i = t; i < NCH * 32; i += blockDim.x) {
        int c = i >> 5, o = i & 31;
        float wv;
        if (c < 54)       wv = w1[o * 64 + 10 + c];
        else if (c == 54) wv = w1[o * 64 + 9];
        else              wv = w1[o * 64 + 3 + (c - 55)] - w1[o * 64 + 6 + (c - 55)];
        g_prep.ws[i] = wv * s1[o];
    }
    for (int i = t; i < 32 * 32; i += blockDim.x) {
        int c = i >> 5, o = i & 31;
        float wm = w2[o * 70 + c] * s2[o];
        float wsn = w2[o * 70 + 35 + c] * s2[o] * 0.0625f;
        g_prep.w2c[i] = make_float2(wm, wsn);
    }
    if (t < 32) {
        int o = t;
        g_prep.wep4[o] = make_float4(
            (w1[o * 64 + 0] + w1[o * 64 + 6]) * s1[o],
            (w1[o * 64 + 1] + w1[o * 64 + 7]) * s1[o],
            (w1[o * 64 + 2] + w1[o * 64 + 8]) * s1[o],
            bf1[o]);
        g_prep.w2e4[o] = make_float4(
            (w2[o * 70 + 32] + w2[o * 70 + 67]) * s2[o],
            (w2[o * 70 + 33] + w2[o * 70 + 68]) * s2[o],
            (w2[o * 70 + 34] + w2[o * 70 + 69]) * s2[o],
            bf2[o]);
    }
}

// ---------------- dynamic smem layout (floats) ------------------------------
// per-warp region (WSTRIDE floats, 128B aligned):
//   [0,1728)     img TMA box: [54 ch][2 units][16 k]
//   [1728,1760)  dist: [2 units][16]
//   [1760,1856)  nb:   [2 units][3 rows][16]
// then w2c (2048), out (32*17=544), mbarriers (8 warps * 2)
#define WSTRIDE 1856
#define W2C_OFF (WARPS * WSTRIDE)            // 14848
#define OUT_OFF (W2C_OFF + 2048)             // 16896
#define MBAR_OFF (OUT_OFF + 544)             // 17440
#define SMEM_FLOATS (MBAR_OFF + 16)          // 17456
#define SMEM_BYTES  (SMEM_FLOATS * 4)        // 69824
#define TMA_BYTES (CIMG * UPW * KNN * 4 + UPW * KNN * 4)   // 6912 + 128 = 7040

__global__ __launch_bounds__(THREADS, 2) void pif_main(
    const __grid_constant__ CUtensorMap tmap_img,
    const __grid_constant__ CUtensorMap tmap_dist,
    const float* __restrict__ points, const int* __restrict__ idx,
    float* __restrict__ out)
{
    extern __shared__ float smem[];
    float2* s_w2c = (float2*)(smem + W2C_OFF);
    float*  s_out = smem + OUT_OFF;

    const int t    = threadIdx.x;
    const int lane = t & 31, wrp = t >> 5;

    const int b  = blockIdx.x >> 10;              // 1024 blocks per batch
    const int n0 = (blockIdx.x & 1023) * NB;
    const int nw = n0 + wrp * UPW;                // this warp's first unit

    float* xs = smem + wrp * WSTRIDE;
    const unsigned mbar = (unsigned)__cvta_generic_to_shared(smem + MBAR_OFF + wrp * 2);

    // ---- kick off TMA first (img 4D box [16,2,54,1] + dist 3D box [16,2,1])
    if (lane == 0) {
        asm volatile("mbarrier.init.shared.b64 [%0], 1;" :: "r"(mbar) : "memory");
    }
    __syncwarp();
    asm volatile("fence.proxy.async.shared::cta;" ::: "memory");
    if (lane == 0) {
        asm volatile("mbarrier.arrive.expect_tx.shared.b64 _, [%0], %1;"
                     :: "r"(mbar), "r"((unsigned)TMA_BYTES) : "memory");
        unsigned dimg = (unsigned)__cvta_generic_to_shared(xs);
        asm volatile(
            "cp.async.bulk.tensor.4d.shared::cta.global.tile.mbarrier::complete_tx::bytes "
            "[%0], [%1, {%2, %3, %4, %5}], [%6];"
            :: "r"(dimg), "l"(&tmap_img),
               "r"(0), "r"(nw), "r"(0), "r"(b), "r"(mbar) : "memory");
        unsigned ddst = (unsigned)__cvta_generic_to_shared(xs + 1728);
        asm volatile(
            "cp.async.bulk.tensor.3d.shared::cta.global.tile.mbarrier::complete_tx::bytes "
            "[%0], [%1, {%2, %3, %4}], [%5];"
            :: "r"(ddst), "l"(&tmap_dist),
               "r"(0), "r"(nw), "r"(b), "r"(mbar) : "memory");
    }

    // ---- while TMA flies: weights to smem/regs + nb gather + ep loads ------
    {
        const float4* src = (const float4*)g_prep.w2c;
        float4* dst = (float4*)(smem + W2C_OFF);
        for (int i = t; i < 512; i += THREADS) dst[i] = src[i];
    }
    float wreg[NCH];
#pragma unroll
    for (int c = 0; c < NCH; c++) wreg[c] = g_prep.ws[c * 32 + lane];
    const float4 wep = g_prep.wep4[lane];
    const float4 w2e = g_prep.w2e4[lane];

    const float* pts_b = points + b * (NPTS * 3);
    const int*   idx_b = idx    + b * (NPTS * KNN);
    float*       out_b = out    + b * (32 * NPTS);

    // nb gather: lanes 0..15 fetch neighbor xyz for both units
#pragma unroll
    for (int u = 0; u < UPW; u++) {
        if (lane < 16) {
            int j = idx_b[(nw + u) * KNN + lane];
            float p0 = pts_b[j * 3 + 0];
            float p1 = pts_b[j * 3 + 1];
            float p2 = pts_b[j * 3 + 2];
            float* r = xs + 1760 + u * 48 + lane;
            r[0]  = p0;
            r[16] = p1;
            r[32] = p2;
        }
    }
    float ep0[UPW], ep1[UPW], ep2[UPW];
#pragma unroll
    for (int u = 0; u < UPW; u++) {
        ep0[u] = pts_b[(nw + u) * 3 + 0];
        ep1[u] = pts_b[(nw + u) * 3 + 1];
        ep2[u] = pts_b[(nw + u) * 3 + 2];
    }
    __syncwarp();                     // nb rows visible within warp

    // ---- wait for TMA completion (acquire) --------------------------------
    {
        unsigned done;
        asm volatile(
            "{\n\t"
            ".reg .pred p;\n\t"
            "mbarrier.try_wait.parity.acquire.cta.shared::cta.b64 p, [%1], 0;\n\t"
            "selp.b32 %0, 1, 0, p;\n\t"
            "}"
            : "=r"(done) : "r"(mbar) : "memory");
        if (!done) {
            asm volatile(
                "{\n\t"
                ".reg .pred P1;\n\t"
                "WL_%=:\n\t"
                "mbarrier.try_wait.parity.acquire.cta.shared::cta.b64 P1, [%0], 0, 0x989680;\n\t"
                "@P1 bra.uni WD_%=;\n\t"
                "bra.uni WL_%=;\n\t"
                "WD_%=:\n\t"
                "}"
                :: "r"(mbar) : "memory");
        }
    }

    float2 hreg[UPW];                 // pooled (max, sum) per unit, lane = o
    float  e2v[UPW];

#pragma unroll
    for (int u = 0; u < UPW; u++) {
        e2v[u] = fmaf(w2e.x, ep0[u], fmaf(w2e.y, ep1[u], fmaf(w2e.z, ep2[u], w2e.w)));

        const float e = fmaf(wep.x, ep0[u], fmaf(wep.y, ep1[u], fmaf(wep.z, ep2[u], wep.w)));
        float2 acc[8];
#pragma unroll
        for (int r = 0; r < 8; r++) acc[r] = make_float2(e, e);

#define ROW(BASE, WIDX)                                                       \
        {                                                                     \
            const float2 wd = dup2(wreg[WIDX]);                               \
            const float4* xp = reinterpret_cast<const float4*>(BASE);         \
            float4 x0 = xp[0], x1 = xp[1], x2 = xp[2], x3 = xp[3];            \
            acc[0] = ffma2(wd, make_float2(x0.x, x0.y), acc[0]);              \
            acc[1] = ffma2(wd, make_float2(x0.z, x0.w), acc[1]);              \
            acc[2] = ffma2(wd, make_float2(x1.x, x1.y), acc[2]);              \
            acc[3] = ffma2(wd, make_float2(x1.z, x1.w), acc[3]);              \
            acc[4] = ffma2(wd, make_float2(x2.x, x2.y), acc[4]);              \
            acc[5] = ffma2(wd, make_float2(x2.z, x2.w), acc[5]);              \
            acc[6] = ffma2(wd, make_float2(x3.x, x3.y), acc[6]);              \
            acc[7] = ffma2(wd, make_float2(x3.z, x3.w), acc[7]);              \
        }

        // img channels: TMA box layout [c][u][k] -> base xs + (c*2+u)*16
        const float* xc = xs + u * KNN;
#pragma unroll
        for (int c = 0; c < CIMG; c++) ROW(xc + c * (UPW * KNN), c)
        ROW(xs + 1728 + u * KNN, 54)                       // dist
        ROW(xs + 1760 + u * 48 + 0,  55)                   // nb0
        ROW(xs + 1760 + u * 48 + 16, 56)                   // nb1
        ROW(xs + 1760 + u * 48 + 32, 57)                   // nb2
#undef ROW

        // ReLU + in-register pool over 16 k values
        float2 mx = make_float2(fmaxf(acc[0].x, 0.f), fmaxf(acc[0].y, 0.f));
        float2 sm = mx;
#pragma unroll
        for (int r = 1; r < 8; r++) {
            float ax = fmaxf(acc[r].x, 0.f), ay = fmaxf(acc[r].y, 0.f);
            mx.x = fmaxf(mx.x, ax); mx.y = fmaxf(mx.y, ay);
            sm.x += ax;             sm.y += ay;
        }
        hreg[u] = make_float2(fmaxf(mx.x, mx.y), sm.x + sm.y);
    }

    // ---- conv2 for both units: w2c read once per warp, h via shfl ----------
    {
        float2 a0 = make_float2(e2v[0], 0.f);
        float2 a1 = make_float2(e2v[1], 0.f);
#pragma unroll 8
        for (int i = 0; i < 32; i++) {
            float2 w = s_w2c[i * 32 + lane];
            float2 h0 = make_float2(__shfl_sync(0xffffffffu, hreg[0].x, i),
                                    __shfl_sync(0xffffffffu, hreg[0].y, i));
            float2 h1 = make_float2(__shfl_sync(0xffffffffu, hreg[1].x, i),
                                    __shfl_sync(0xffffffffu, hreg[1].y, i));
            a0 = ffma2(w, h0, a0);
            a1 = ffma2(w, h1, a1);
        }
        float* so = s_out + lane * 17 + wrp * 2;
        so[0] = fmaxf(a0.x + a0.y, 0.0f);
        so[1] = fmaxf(a1.x + a1.y, 0.0f);
    }

    // block-wide sync, then coalesced float2 stores (16 n per o row)
    __syncthreads();
    {
        int o = t >> 3, j = (t & 7) * 2;
        float2 v = make_float2(s_out[o * 17 + j], s_out[o * 17 + j + 1]);
        *reinterpret_cast<float2*>(out_b + o * NPTS + n0 + j) = v;
    }
}

// ---------------- launch ----------------------------------------------------
typedef CUresult (*PFN_encodeTiled)(
    CUtensorMap*, CUtensorMapDataType, cuuint32_t, void*,
    const cuuint64_t*, const cuuint64_t*, const cuuint32_t*, const cuuint32_t*,
    CUtensorMapInterleave, CUtensorMapSwizzle, CUtensorMapL2promotion,
    CUtensorMapFloatOOBfill);

extern "C" void kernel_launch(void* const* d_in, const int* in_sizes, int n_in,
                              void* d_out, int out_size)
{
    const float* points = (const float*)d_in[0];
    void*        img    = (void*)d_in[1];
    void*        dist   = (void*)d_in[2];
    const int*   idx    = (const int*)  d_in[3];

    prep_kernel<<<1, 256>>>(
        (const float*)d_in[4],  (const float*)d_in[5],
        (const float*)d_in[6],  (const float*)d_in[7],
        (const float*)d_in[8],  (const float*)d_in[9],
        (const float*)d_in[10], (const float*)d_in[11],
        (const float*)d_in[12], (const float*)d_in[13],
        (const float*)d_in[14], (const float*)d_in[15]);

    // driver entry point via runtime (no -lcuda link needed)
    PFN_encodeTiled encode = nullptr;
    {
        void* fn = nullptr;
#if CUDART_VERSION >= 12000
        cudaDriverEntryPointQueryResult qr;
        cudaGetDriverEntryPoint("cuTensorMapEncodeTiled", &fn, cudaEnableDefault, &qr);
#else
        cudaGetDriverEntryPoint("cuTensorMapEncodeTiled", &fn, cudaEnableDefault);
#endif
        encode = (PFN_encodeTiled)fn;
    }

    CUtensorMap tmap_img{}, tmap_dist{};
    {
        cuuint64_t dims[4]    = {KNN, NPTS, CIMG, 4};
        cuuint64_t strides[3] = {KNN * 4ull,
                                 (cuuint64_t)NPTS * KNN * 4ull,
                                 (cuuint64_t)CIMG * NPTS * KNN * 4ull};
        cuuint32_t box[4]     = {KNN, UPW, CIMG, 1};
        cuuint32_t estr[4]    = {1, 1, 1, 1};
        encode(&tmap_img, CU_TENSOR_MAP_DATA_TYPE_FLOAT32, 4, img,
               dims, strides, box, estr,
               CU_TENSOR_MAP_INTERLEAVE_NONE, CU_TENSOR_MAP_SWIZZLE_NONE,
               CU_TENSOR_MAP_L2_PROMOTION_L2_128B,
               CU_TENSOR_MAP_FLOAT_OOB_FILL_NONE);
    }
    {
        cuuint64_t dims[3]    = {KNN, NPTS, 4};
        cuuint64_t strides[2] = {KNN * 4ull, (cuuint64_t)NPTS * KNN * 4ull};
        cuuint32_t box[3]     = {KNN, UPW, 1};
        cuuint32_t estr[3]    = {1, 1, 1};
        encode(&tmap_dist, CU_TENSOR_MAP_DATA_TYPE_FLOAT32, 3, dist,
               dims, strides, box, estr,
               CU_TENSOR_MAP_INTERLEAVE_NONE, CU_TENSOR_MAP_SWIZZLE_NONE,
               CU_TENSOR_MAP_L2_PROMOTION_L2_128B,
               CU_TENSOR_MAP_FLOAT_OOB_FILL_NONE);
    }

    cudaFuncSetAttribute(pif_main, cudaFuncAttributeMaxDynamicSharedMemorySize,
                         SMEM_BYTES);
    pif_main<<<NBLOCKS, THREADS, SMEM_BYTES>>>(tmap_img, tmap_dist,
                                               points, idx, (float*)d_out);
}

// round 9
// speedup vs baseline: 1.0579x; 1.0018x over previous
#include <cuda_runtime.h>
#include <cuda.h>

#define NPTS 16384
#define KNN  16
#define CIMG 54
#define NCH  58                      // 54 img + dist + nb0..2
#define CSTRIDE (NPTS * KNN)
#define THREADS 256
#define WARPS 8
#define UPW 2                        // n-units per warp
#define NB (WARPS * UPW)             // 16 units per block
#define NBLOCKS ((4 * NPTS) / NB)    // 4096

// ---------------- folded-weight scratch (device global; no allocs) ----------
struct Prep {
    float  ws[NCH * 32];     // [row c][o]: conv1 weight, BN-folded
    float2 w2c[32 * 32];     // [i][o2] = (w2_max, w2_mean/16), BN-folded
    float4 wep4[32];         // per o: (wep0, wep1, wep2, bias1_folded)
    float4 w2e4[32];         // per o2: (w2ep0, w2ep1, w2ep2, bias2_folded)
};
__device__ Prep g_prep;

// ---------------- packed fp32x2 helpers -------------------------------------
union F2U { float2 f; unsigned long long u; };
__device__ __forceinline__ float2 ffma2(float2 a, float2 b, float2 c) {
    F2U A, B, C, D;
    A.f = a; B.f = b; C.f = c;
    asm("fma.rn.f32x2 %0, %1, %2, %3;" : "=l"(D.u) : "l"(A.u), "l"(B.u), "l"(C.u));
    return D.f;
}
__device__ __forceinline__ float2 dup2(float w) {
    F2U D;
    asm("mov.b64 %0, {%1, %1};" : "=l"(D.u) : "f"(w));
    return D.f;
}

// ---------------- prep: fold BN + concat algebra into weights ---------------
__global__ void prep_kernel(
    const float* __restrict__ w1, const float* __restrict__ b1,
    const float* __restrict__ g1, const float* __restrict__ be1,
    const float* __restrict__ m1, const float* __restrict__ v1,
    const float* __restrict__ w2, const float* __restrict__ b2,
    const float* __restrict__ g2, const float* __restrict__ be2,
    const float* __restrict__ m2, const float* __restrict__ v2)
{
    __shared__ float s1[32], s2[32], bf1[32], bf2[32];
    int t = threadIdx.x;
    if (t < 32) {
        float sc = g1[t] / sqrtf(v1[t] + 1e-6f);
        s1[t]  = sc;
        bf1[t] = (b1[t] - m1[t]) * sc + be1[t];
        float sc2 = g2[t] / sqrtf(v2[t] + 1e-6f);
        s2[t]  = sc2;
        bf2[t] = (b2[t] - m2[t]) * sc2 + be2[t];
    }
    __syncthreads();

    // conv1 rows: 0..53 img (w1 col 10+c), 54 dist (col 9), 55..57 nb (col 3+c - col 6+c)
    for (int i = t; i < NCH * 32; i += blockDim.x) {
        int c = i >> 5, o = i & 31;
        float wv;
        if (c < 54)       wv = w1[o * 64 + 10 + c];
        else if (c == 54) wv = w1[o * 64 + 9];
        else              wv = w1[o * 64 + 3 + (c - 55)] - w1[o * 64 + 6 + (c - 55)];
        g_prep.ws[i] = wv * s1[o];
    }
    for (int i = t; i < 32 * 32; i += blockDim.x) {
        int c = i >> 5, o = i & 31;
        float wm = w2[o * 70 + c] * s2[o];
        float wsn = w2[o * 70 + 35 + c] * s2[o] * 0.0625f;
        g_prep.w2c[i] = make_float2(wm, wsn);
    }
    if (t < 32) {
        int o = t;
        g_prep.wep4[o] = make_float4(
            (w1[o * 64 + 0] + w1[o * 64 + 6]) * s1[o],
            (w1[o * 64 + 1] + w1[o * 64 + 7]) * s1[o],
            (w1[o * 64 + 2] + w1[o * 64 + 8]) * s1[o],
            bf1[o]);
        g_prep.w2e4[o] = make_float4(
            (w2[o * 70 + 32] + w2[o * 70 + 67]) * s2[o],
            (w2[o * 70 + 33] + w2[o * 70 + 68]) * s2[o],
            (w2[o * 70 + 34] + w2[o * 70 + 69]) * s2[o],
            bf2[o]);
    }
}

// ---------------- dynamic smem layout (floats) ------------------------------
// per-warp region (WSTRIDE floats, 128B aligned):
//   [0,1728)     img TMA box: [54 ch][2 units][16 k]
//   [1728,1760)  dist: [2 units][16]
//   [1760,1856)  nb:   [2 units][3 rows][16]
// then w2c (2048), out (32*17=544), mbarriers (8 warps * 2)
#define WSTRIDE 1856
#define W2C_OFF (WARPS * WSTRIDE)            // 14848
#define OUT_OFF (W2C_OFF + 2048)             // 16896
#define MBAR_OFF (OUT_OFF + 544)             // 17440
#define SMEM_FLOATS (MBAR_OFF + 16)          // 17456
#define SMEM_BYTES  (SMEM_FLOATS * 4)        // 69824
#define TMA_BYTES (CIMG * UPW * KNN * 4 + UPW * KNN * 4)   // 6912 + 128 = 7040

__global__ __launch_bounds__(THREADS, 2) void pif_main(
    const __grid_constant__ CUtensorMap tmap_img,
    const __grid_constant__ CUtensorMap tmap_dist,
    const float* __restrict__ points, const int* __restrict__ idx,
    float* __restrict__ out)
{
    extern __shared__ float smem[];
    float2* s_w2c = (float2*)(smem + W2C_OFF);
    float*  s_out = smem + OUT_OFF;

    const int t    = threadIdx.x;
    const int lane = t & 31, wrp = t >> 5;

    const int b  = blockIdx.x >> 10;              // 1024 blocks per batch
    const int n0 = (blockIdx.x & 1023) * NB;
    const int nw = n0 + wrp * UPW;                // this warp's first unit

    float* xs = smem + wrp * WSTRIDE;
    const unsigned mbar = (unsigned)__cvta_generic_to_shared(smem + MBAR_OFF + wrp * 2);

    // ---- kick off TMA first (img 4D box [16,2,54,1] + dist 3D box [16,2,1])
    if (lane == 0) {
        asm volatile("mbarrier.init.shared.b64 [%0], 1;" :: "r"(mbar) : "memory");
    }
    __syncwarp();
    asm volatile("fence.proxy.async.shared::cta;" ::: "memory");
    if (lane == 0) {
        asm volatile("mbarrier.arrive.expect_tx.shared.b64 _, [%0], %1;"
                     :: "r"(mbar), "r"((unsigned)TMA_BYTES) : "memory");
        unsigned dimg = (unsigned)__cvta_generic_to_shared(xs);
        asm volatile(
            "cp.async.bulk.tensor.4d.shared::cta.global.tile.mbarrier::complete_tx::bytes "
            "[%0], [%1, {%2, %3, %4, %5}], [%6];"
            :: "r"(dimg), "l"(&tmap_img),
               "r"(0), "r"(nw), "r"(0), "r"(b), "r"(mbar) : "memory");
        unsigned ddst = (unsigned)__cvta_generic_to_shared(xs + 1728);
        asm volatile(
            "cp.async.bulk.tensor.3d.shared::cta.global.tile.mbarrier::complete_tx::bytes "
            "[%0], [%1, {%2, %3, %4}], [%5];"
            :: "r"(ddst), "l"(&tmap_dist),
               "r"(0), "r"(nw), "r"(b), "r"(mbar) : "memory");
    }

    // ---- while TMA flies: weights to smem/regs + nb gather + ep loads ------
    {
        const float4* src = (const float4*)g_prep.w2c;
        float4* dst = (float4*)(smem + W2C_OFF);
        for (int i = t; i < 512; i += THREADS) dst[i] = src[i];
    }
    float wreg[NCH];
#pragma unroll
    for (int c = 0; c < NCH; c++) wreg[c] = g_prep.ws[c * 32 + lane];
    const float4 wep = g_prep.wep4[lane];
    const float4 w2e = g_prep.w2e4[lane];

    const float* pts_b = points + b * (NPTS * 3);
    const int*   idx_b = idx    + b * (NPTS * KNN);
    float*       out_b = out    + b * (32 * NPTS);

    // nb gather: lanes 0..15 fetch neighbor xyz for both units
#pragma unroll
    for (int u = 0; u < UPW; u++) {
        if (lane < 16) {
            int j = idx_b[(nw + u) * KNN + lane];
            float p0 = pts_b[j * 3 + 0];
            float p1 = pts_b[j * 3 + 1];
            float p2 = pts_b[j * 3 + 2];
            float* r = xs + 1760 + u * 48 + lane;
            r[0]  = p0;
            r[16] = p1;
            r[32] = p2;
        }
    }
    float ep0[UPW], ep1[UPW], ep2[UPW];
#pragma unroll
    for (int u = 0; u < UPW; u++) {
        ep0[u] = pts_b[(nw + u) * 3 + 0];
        ep1[u] = pts_b[(nw + u) * 3 + 1];
        ep2[u] = pts_b[(nw + u) * 3 + 2];
    }
    __syncwarp();                     // nb rows visible within warp

    // ---- wait for TMA completion (acquire) --------------------------------
    {
        unsigned done;
        asm volatile(
            "{\n\t"
            ".reg .pred p;\n\t"
            "mbarrier.try_wait.parity.acquire.cta.shared::cta.b64 p, [%1], 0;\n\t"
            "selp.b32 %0, 1, 0, p;\n\t"
            "}"
            : "=r"(done) : "r"(mbar) : "memory");
        if (!done) {
            asm volatile(
                "{\n\t"
                ".reg .pred P1;\n\t"
                "WL_%=:\n\t"
                "mbarrier.try_wait.parity.acquire.cta.shared::cta.b64 P1, [%0], 0, 0x989680;\n\t"
                "@P1 bra.uni WD_%=;\n\t"
                "bra.uni WL_%=;\n\t"
                "WD_%=:\n\t"
                "}"
                :: "r"(mbar) : "memory");
        }
    }

    float2 hreg[UPW];                 // pooled (max, sum) per unit, lane = o
    float  e2v[UPW];

#pragma unroll
    for (int u = 0; u < UPW; u++) {
        e2v[u] = fmaf(w2e.x, ep0[u], fmaf(w2e.y, ep1[u], fmaf(w2e.z, ep2[u], w2e.w)));

        const float e = fmaf(wep.x, ep0[u], fmaf(wep.y, ep1[u], fmaf(wep.z, ep2[u], wep.w)));
        float2 acc[8];
#pragma unroll
        for (int r = 0; r < 8; r++) acc[r] = make_float2(e, e);

#define ROW(BASE, WIDX)                                                       \
        {                                                                     \
            const float2 wd = dup2(wreg[WIDX]);                               \
            const float4* xp = reinterpret_cast<const float4*>(BASE);         \
            float4 x0 = xp[0], x1 = xp[1], x2 = xp[2], x3 = xp[3];            \
            acc[0] = ffma2(wd, make_float2(x0.x, x0.y), acc[0]);              \
            acc[1] = ffma2(wd, make_float2(x0.z, x0.w), acc[1]);              \
            acc[2] = ffma2(wd, make_float2(x1.x, x1.y), acc[2]);              \
            acc[3] = ffma2(wd, make_float2(x1.z, x1.w), acc[3]);              \
            acc[4] = ffma2(wd, make_float2(x2.x, x2.y), acc[4]);              \
            acc[5] = ffma2(wd, make_float2(x2.z, x2.w), acc[5]);              \
            acc[6] = ffma2(wd, make_float2(x3.x, x3.y), acc[6]);              \
            acc[7] = ffma2(wd, make_float2(x3.z, x3.w), acc[7]);              \
        }

        // img channels: TMA box layout [c][u][k] -> base xs + (c*2+u)*16
        const float* xc = xs + u * KNN;
#pragma unroll
        for (int c = 0; c < CIMG; c++) ROW(xc + c * (UPW * KNN), c)
        ROW(xs + 1728 + u * KNN, 54)                       // dist
        ROW(xs + 1760 + u * 48 + 0,  55)                   // nb0
        ROW(xs + 1760 + u * 48 + 16, 56)                   // nb1
        ROW(xs + 1760 + u * 48 + 32, 57)                   // nb2
#undef ROW

        // ReLU + in-register pool over 16 k values
        float2 mx = make_float2(fmaxf(acc[0].x, 0.f), fmaxf(acc[0].y, 0.f));
        float2 sm = mx;
#pragma unroll
        for (int r = 1; r < 8; r++) {
            float ax = fmaxf(acc[r].x, 0.f), ay = fmaxf(acc[r].y, 0.f);
            mx.x = fmaxf(mx.x, ax); mx.y = fmaxf(mx.y, ay);
            sm.x += ax;             sm.y += ay;
        }
        hreg[u] = make_float2(fmaxf(mx.x, mx.y), sm.x + sm.y);
    }

    // ---- conv2 for both units: w2c read once per warp, h via shfl ----------
    {
        float2 a0 = make_float2(e2v[0], 0.f);
        float2 a1 = make_float2(e2v[1], 0.f);
#pragma unroll 8
        for (int i = 0; i < 32; i++) {
            float2 w = s_w2c[i * 32 + lane];
            float2 h0 = make_float2(__shfl_sync(0xffffffffu, hreg[0].x, i),
                                    __shfl_sync(0xffffffffu, hreg[0].y, i));
            float2 h1 = make_float2(__shfl_sync(0xffffffffu, hreg[1].x, i),
                                    __shfl_sync(0xffffffffu, hreg[1].y, i));
            a0 = ffma2(w, h0, a0);
            a1 = ffma2(w, h1, a1);
        }
        float* so = s_out + lane * 17 + wrp * 2;
        so[0] = fmaxf(a0.x + a0.y, 0.0f);
        so[1] = fmaxf(a1.x + a1.y, 0.0f);
    }

    // block-wide sync, then coalesced float2 stores (16 n per o row)
    __syncthreads();
    {
        int o = t >> 3, j = (t & 7) * 2;
        float2 v = make_float2(s_out[o * 17 + j], s_out[o * 17 + j + 1]);
        *reinterpret_cast<float2*>(out_b + o * NPTS + n0 + j) = v;
    }
}

// ---------------- launch ----------------------------------------------------
typedef CUresult (*PFN_encodeTiled)(
    CUtensorMap*, CUtensorMapDataType, cuuint32_t, void*,
    const cuuint64_t*, const cuuint64_t*, const cuuint32_t*, const cuuint32_t*,
    CUtensorMapInterleave, CUtensorMapSwizzle, CUtensorMapL2promotion,
    CUtensorMapFloatOOBfill);

extern "C" void kernel_launch(void* const* d_in, const int* in_sizes, int n_in,
                              void* d_out, int out_size)
{
    const float* points = (const float*)d_in[0];
    void*        img    = (void*)d_in[1];
    void*        dist   = (void*)d_in[2];
    const int*   idx    = (const int*)  d_in[3];

    prep_kernel<<<1, 256>>>(
        (const float*)d_in[4],  (const float*)d_in[5],
        (const float*)d_in[6],  (const float*)d_in[7],
        (const float*)d_in[8],  (const float*)d_in[9],
        (const float*)d_in[10], (const float*)d_in[11],
        (const float*)d_in[12], (const float*)d_in[13],
        (const float*)d_in[14], (const float*)d_in[15]);

    // driver entry point via runtime (no -lcuda link needed)
    PFN_encodeTiled encode = nullptr;
    {
        void* fn = nullptr;
#if CUDART_VERSION >= 12000
        cudaDriverEntryPointQueryResult qr;
        cudaGetDriverEntryPoint("cuTensorMapEncodeTiled", &fn, cudaEnableDefault, &qr);
#else
        cudaGetDriverEntryPoint("cuTensorMapEncodeTiled", &fn, cudaEnableDefault);
#endif
        encode = (PFN_encodeTiled)fn;
    }

    CUtensorMap tmap_img{}, tmap_dist{};
    {
        cuuint64_t dims[4]    = {KNN, NPTS, CIMG, 4};
        cuuint64_t strides[3] = {KNN * 4ull,
                                 (cuuint64_t)NPTS * KNN * 4ull,
                                 (cuuint64_t)CIMG * NPTS * KNN * 4ull};
        cuuint32_t box[4]     = {KNN, UPW, CIMG, 1};
        cuuint32_t estr[4]    = {1, 1, 1, 1};
        encode(&tmap_img, CU_TENSOR_MAP_DATA_TYPE_FLOAT32, 4, img,
               dims, strides, box, estr,
               CU_TENSOR_MAP_INTERLEAVE_NONE, CU_TENSOR_MAP_SWIZZLE_NONE,
               CU_TENSOR_MAP_L2_PROMOTION_L2_128B,
               CU_TENSOR_MAP_FLOAT_OOB_FILL_NONE);
    }
    {
        cuuint64_t dims[3]    = {KNN, NPTS, 4};
        cuuint64_t strides[2] = {KNN * 4ull, (cuuint64_t)NPTS * KNN * 4ull};
        cuuint32_t box[3]     = {KNN, UPW, 1};
        cuuint32_t estr[3]    = {1, 1, 1};
        encode(&tmap_dist, CU_TENSOR_MAP_DATA_TYPE_FLOAT32, 3, dist,
               dims, strides, box, estr,
               CU_TENSOR_MAP_INTERLEAVE_NONE, CU_TENSOR_MAP_SWIZZLE_NONE,
               CU_TENSOR_MAP_L2_PROMOTION_L2_128B,
               CU_TENSOR_MAP_FLOAT_OOB_FILL_NONE);
    }

    cudaFuncSetAttribute(pif_main, cudaFuncAttributeMaxDynamicSharedMemorySize,
                         SMEM_BYTES);
    pif_main<<<NBLOCKS, THREADS, SMEM_BYTES>>>(tmap_img, tmap_dist,
                                               points, idx, (float*)d_out);
}

// round 10
// speedup vs baseline: 1.3130x; 1.2412x over previous
#include <cuda_runtime.h>
#include <cuda.h>

#define NPTS 16384
#define KNN  16
#define CIMG 54
#define NCH  58                      // 54 img + dist + nb0..2
#define THREADS 256
#define WARPS 8
#define UPW 2                        // n-units per warp
#define NB (WARPS * UPW)             // 16 units per block
#define NBLOCKS ((4 * NPTS) / NB)    // 4096

// ---------------- folded-weight scratch (device global; no allocs) ----------
struct Prep {
    float  ws[NCH * 32];     // [row c][o]: conv1 weight, BN-folded
    float2 w2c[32 * 32];     // [i][o2] = (w2_max, w2_mean/16), BN-folded
    float4 wep4[32];         // per o: (wep0, wep1, wep2, bias1_folded)
    float4 w2e4[32];         // per o2: (w2ep0, w2ep1, w2ep2, bias2_folded)
};
__device__ Prep g_prep;

// ---------------- packed fp32x2 helpers -------------------------------------
union F2U { float2 f; unsigned long long u; };
__device__ __forceinline__ float2 ffma2(float2 a, float2 b, float2 c) {
    F2U A, B, C, D;
    A.f = a; B.f = b; C.f = c;
    asm("fma.rn.f32x2 %0, %1, %2, %3;" : "=l"(D.u) : "l"(A.u), "l"(B.u), "l"(C.u));
    return D.f;
}
__device__ __forceinline__ float2 dup2(float w) {
    F2U D;
    asm("mov.b64 %0, {%1, %1};" : "=l"(D.u) : "f"(w));
    return D.f;
}
__device__ __forceinline__ float2 relu2(float2 a) {
    return make_float2(fmaxf(a.x, 0.f), fmaxf(a.y, 0.f));
}
__device__ __forceinline__ float2 max2(float2 a, float2 b) {
    return make_float2(fmaxf(a.x, b.x), fmaxf(a.y, b.y));
}
__device__ __forceinline__ float2 add2(float2 a, float2 b) {
    return make_float2(a.x + b.x, a.y + b.y);
}
__device__ __forceinline__ float2 shfl2(float2 v, int m) {
    return make_float2(__shfl_xor_sync(0xffffffffu, v.x, m),
                       __shfl_xor_sync(0xffffffffu, v.y, m));
}

// ---------------- prep: fold BN + concat algebra into weights ---------------
__global__ void prep_kernel(
    const float* __restrict__ w1, const float* __restrict__ b1,
    const float* __restrict__ g1, const float* __restrict__ be1,
    const float* __restrict__ m1, const float* __restrict__ v1,
    const float* __restrict__ w2, const float* __restrict__ b2,
    const float* __restrict__ g2, const float* __restrict__ be2,
    const float* __restrict__ m2, const float* __restrict__ v2)
{
    __shared__ float s1[32], s2[32], bf1[32], bf2[32];
    int t = threadIdx.x;
    if (t < 32) {
        float sc = g1[t] / sqrtf(v1[t] + 1e-6f);
        s1[t]  = sc;
        bf1[t] = (b1[t] - m1[t]) * sc + be1[t];
        float sc2 = g2[t] / sqrtf(v2[t] + 1e-6f);
        s2[t]  = sc2;
        bf2[t] = (b2[t] - m2[t]) * sc2 + be2[t];
    }
    __syncthreads();

    // conv1 rows: 0..53 img (w1 col 10+c), 54 dist (col 9), 55..57 nb (col 3+c - col 6+c)
    for (int i = t; i < NCH * 32; i += blockDim.x) {
        int c = i >> 5, o = i & 31;
        float wv;
        if (c < 54)       wv = w1[o * 64 + 10 + c];
        else if (c == 54) wv = w1[o * 64 + 9];
        else              wv = w1[o * 64 + 3 + (c - 55)] - w1[o * 64 + 6 + (c - 55)];
        g_prep.ws[i] = wv * s1[o];
    }
    for (int i = t; i < 32 * 32; i += blockDim.x) {
        int c = i >> 5, o = i & 31;
        float wm = w2[o * 70 + c] * s2[o];
        float wsn = w2[o * 70 + 35 + c] * s2[o] * 0.0625f;
        g_prep.w2c[i] = make_float2(wm, wsn);
    }
    if (t < 32) {
        int o = t;
        g_prep.wep4[o] = make_float4(
            (w1[o * 64 + 0] + w1[o * 64 + 6]) * s1[o],
            (w1[o * 64 + 1] + w1[o * 64 + 7]) * s1[o],
            (w1[o * 64 + 2] + w1[o * 64 + 8]) * s1[o],
            bf1[o]);
        g_prep.w2e4[o] = make_float4(
            (w2[o * 70 + 32] + w2[o * 70 + 67]) * s2[o],
            (w2[o * 70 + 33] + w2[o * 70 + 68]) * s2[o],
            (w2[o * 70 + 34] + w2[o * 70 + 69]) * s2[o],
            bf2[o]);
    }
}

// ---------------- dynamic smem layout (floats) ------------------------------
// per-warp region xs (WSTRIDE floats):
//   [0,1728)     img TMA box: [54 ch][2 units][16 k]
//   [1728,1760)  dist: [2 units][16]
//   [1760,1856)  nb:   [2 units][3 rows][16]
//   (xs[0..128) reused later for the pooled-h transpose)
// then w1 (1856), w2c (2048), wep (128), out (544), mbarriers (16)
#define WSTRIDE 1856
#define W1_OFF   (WARPS * WSTRIDE)            // 14848
#define W2C_OFF  (W1_OFF + NCH * 32)          // 16704
#define WEP_OFF  (W2C_OFF + 2048)             // 18752
#define OUT_OFF  (WEP_OFF + 128)              // 18880
#define MBAR_OFF (OUT_OFF + 544)              // 19424
#define SMEM_FLOATS (MBAR_OFF + 16)           // 19440
#define SMEM_BYTES  (SMEM_FLOATS * 4)         // 77760
#define TMA_BYTES (CIMG * UPW * KNN * 4 + UPW * KNN * 4)   // 7040

__global__ __launch_bounds__(THREADS, 2) void pif_main(
    const __grid_constant__ CUtensorMap tmap_img,
    const __grid_constant__ CUtensorMap tmap_dist,
    const float* __restrict__ points, const int* __restrict__ idx,
    float* __restrict__ out)
{
    extern __shared__ float smem[];
    float*  s_w1  = smem + W1_OFF;
    float2* s_w2c = (float2*)(smem + W2C_OFF);
    float4* s_wep = (float4*)(smem + WEP_OFF);
    float*  s_out = smem + OUT_OFF;

    const int t    = threadIdx.x;
    const int lane = t & 31, wrp = t >> 5;
    const int uu = lane >> 4;                 // unit within warp pair
    const int og = (lane >> 2) & 3;           // o-group (8 outputs)
    const int kq = lane & 3;                  // k-quad (4 k values)
    const int o0 = og * 8;

    const int b  = blockIdx.x >> 10;          // 1024 blocks per batch
    const int n0 = (blockIdx.x & 1023) * NB;
    const int nw = n0 + wrp * UPW;            // this warp's first unit

    float* xs = smem + wrp * WSTRIDE;
    const unsigned mbar = (unsigned)__cvta_generic_to_shared(smem + MBAR_OFF + wrp * 2);

    // ---- kick off TMA (img 4D box [16,2,54,1] + dist 3D box [16,2,1]) ------
    if (lane == 0) {
        asm volatile("mbarrier.init.shared.b64 [%0], 1;" :: "r"(mbar) : "memory");
    }
    __syncwarp();
    asm volatile("fence.proxy.async.shared::cta;" ::: "memory");
    if (lane == 0) {
        asm volatile("mbarrier.arrive.expect_tx.shared.b64 _, [%0], %1;"
                     :: "r"(mbar), "r"((unsigned)TMA_BYTES) : "memory");
        unsigned dimg = (unsigned)__cvta_generic_to_shared(xs);
        asm volatile(
            "cp.async.bulk.tensor.4d.shared::cta.global.tile.mbarrier::complete_tx::bytes "
            "[%0], [%1, {%2, %3, %4, %5}], [%6];"
            :: "r"(dimg), "l"(&tmap_img),
               "r"(0), "r"(nw), "r"(0), "r"(b), "r"(mbar) : "memory");
        unsigned ddst = (unsigned)__cvta_generic_to_shared(xs + 1728);
        asm volatile(
            "cp.async.bulk.tensor.3d.shared::cta.global.tile.mbarrier::complete_tx::bytes "
            "[%0], [%1, {%2, %3, %4}], [%5];"
            :: "r"(ddst), "l"(&tmap_dist),
               "r"(0), "r"(nw), "r"(b), "r"(mbar) : "memory");
    }

    // ---- while TMA flies: copy folded weights to smem (ws|w2c|wep contiguous)
    {
        const float4* src = (const float4*)&g_prep;
        float4* dst = (float4*)(smem + W1_OFF);
        for (int i = t; i < (NCH * 32 + 2048 + 128) / 4; i += THREADS) dst[i] = src[i];
    }

    const float* pts_b = points + b * (NPTS * 3);
    const int*   idx_b = idx    + b * (NPTS * KNN);
    float*       out_b = out    + b * (32 * NPTS);

    // nb gather: lanes 0..15 fetch neighbor xyz for both units
#pragma unroll
    for (int u = 0; u < UPW; u++) {
        if (lane < 16) {
            int j = idx_b[(nw + u) * KNN + lane];
            float p0 = pts_b[j * 3 + 0];
            float p1 = pts_b[j * 3 + 1];
            float p2 = pts_b[j * 3 + 2];
            float* r = xs + 1760 + u * 48 + lane;
            r[0]  = p0;
            r[16] = p1;
            r[32] = p2;
        }
    }
    // ep for both units (every lane)
    float ep0[UPW], ep1[UPW], ep2[UPW];
#pragma unroll
    for (int u = 0; u < UPW; u++) {
        ep0[u] = pts_b[(nw + u) * 3 + 0];
        ep1[u] = pts_b[(nw + u) * 3 + 1];
        ep2[u] = pts_b[(nw + u) * 3 + 2];
    }

    __syncthreads();                 // weight tables + nb rows visible

    const float4 w2e = g_prep.w2e4[lane];
    float e2v0 = fmaf(w2e.x, ep0[0], fmaf(w2e.y, ep1[0], fmaf(w2e.z, ep2[0], w2e.w)));
    float e2v1 = fmaf(w2e.x, ep0[1], fmaf(w2e.y, ep1[1], fmaf(w2e.z, ep2[1], w2e.w)));

    // conv1 accumulator init: per o-pair ep-term for THIS lane's unit
    const float eu0 = uu ? ep0[1] : ep0[0];
    const float eu1 = uu ? ep1[1] : ep1[0];
    const float eu2 = uu ? ep2[1] : ep2[0];
    float2 acc[16];                  // acc[4*j + op]: k = kq*4+j, o = o0+2op,+1
    {
#pragma unroll
        for (int op = 0; op < 4; op++) {
            float4 wa = s_wep[o0 + 2 * op];
            float4 wb = s_wep[o0 + 2 * op + 1];
            float2 ei = make_float2(
                fmaf(wa.x, eu0, fmaf(wa.y, eu1, fmaf(wa.z, eu2, wa.w))),
                fmaf(wb.x, eu0, fmaf(wb.y, eu1, fmaf(wb.z, eu2, wb.w))));
            acc[op] = ei; acc[4 + op] = ei; acc[8 + op] = ei; acc[12 + op] = ei;
        }
    }

    // ---- wait for TMA completion (acquire) --------------------------------
    {
        unsigned done;
        asm volatile(
            "{\n\t"
            ".reg .pred p;\n\t"
            "mbarrier.try_wait.parity.acquire.cta.shared::cta.b64 p, [%1], 0;\n\t"
            "selp.b32 %0, 1, 0, p;\n\t"
            "}"
            : "=r"(done) : "r"(mbar) : "memory");
        if (!done) {
            asm volatile(
                "{\n\t"
                ".reg .pred P1;\n\t"
                "WL_%=:\n\t"
                "mbarrier.try_wait.parity.acquire.cta.shared::cta.b64 P1, [%0], 0, 0x989680;\n\t"
                "@P1 bra.uni WD_%=;\n\t"
                "bra.uni WL_%=;\n\t"
                "WD_%=:\n\t"
                "}"
                :: "r"(mbar) : "memory");
        }
    }

    // ---- conv1: both units in one pass; distinct-lane reads ----------------
    const int xoff = uu * 16 + kq * 4;        // float offset within a row-pair

#define ROW(XBASE, C)                                                          \
    {                                                                          \
        const float4 wv0 = *(const float4*)(s_w1 + (C) * 32 + o0);             \
        const float4 wv1 = *(const float4*)(s_w1 + (C) * 32 + o0 + 4);         \
        const float4 xv  = *(const float4*)(XBASE);                            \
        float2 xd;                                                             \
        xd = dup2(xv.x);                                                       \
        acc[0]  = ffma2(make_float2(wv0.x, wv0.y), xd, acc[0]);                \
        acc[1]  = ffma2(make_float2(wv0.z, wv0.w), xd, acc[1]);                \
        acc[2]  = ffma2(make_float2(wv1.x, wv1.y), xd, acc[2]);                \
        acc[3]  = ffma2(make_float2(wv1.z, wv1.w), xd, acc[3]);                \
        xd = dup2(xv.y);                                                       \
        acc[4]  = ffma2(make_float2(wv0.x, wv0.y), xd, acc[4]);                \
        acc[5]  = ffma2(make_float2(wv0.z, wv0.w), xd, acc[5]);                \
        acc[6]  = ffma2(make_float2(wv1.x, wv1.y), xd, acc[6]);                \
        acc[7]  = ffma2(make_float2(wv1.z, wv1.w), xd, acc[7]);                \
        xd = dup2(xv.z);                                                       \
        acc[8]  = ffma2(make_float2(wv0.x, wv0.y), xd, acc[8]);                \
        acc[9]  = ffma2(make_float2(wv0.z, wv0.w), xd, acc[9]);                \
        acc[10] = ffma2(make_float2(wv1.x, wv1.y), xd, acc[10]);               \
        acc[11] = ffma2(make_float2(wv1.z, wv1.w), xd, acc[11]);               \
        xd = dup2(xv.w);                                                       \
        acc[12] = ffma2(make_float2(wv0.x, wv0.y), xd, acc[12]);               \
        acc[13] = ffma2(make_float2(wv0.z, wv0.w), xd, acc[13]);               \
        acc[14] = ffma2(make_float2(wv1.x, wv1.y), xd, acc[14]);               \
        acc[15] = ffma2(make_float2(wv1.z, wv1.w), xd, acc[15]);               \
    }

    {
        const float* xc = xs + xoff;
#pragma unroll 6
        for (int c = 0; c < CIMG; c++) ROW(xc + c * (UPW * KNN), c)
        ROW(xs + 1728 + xoff, 54)                          // dist
        {
            const float* nbb = xs + 1760 + uu * 48 + kq * 4;
            ROW(nbb + 0,  55)                              // nb0
            ROW(nbb + 16, 56)                              // nb1
            ROW(nbb + 32, 57)                              // nb2
        }
    }
#undef ROW

    // ---- ReLU + pool: in-lane over 4 k, then 2 shfl rounds over kq ---------
    float2 mx[4], sm[4];
#pragma unroll
    for (int op = 0; op < 4; op++) {
        float2 a0 = relu2(acc[op]),      a1 = relu2(acc[4 + op]);
        float2 a2 = relu2(acc[8 + op]),  a3 = relu2(acc[12 + op]);
        mx[op] = max2(max2(a0, a1), max2(a2, a3));
        sm[op] = add2(add2(a0, a1), add2(a2, a3));
    }
#pragma unroll
    for (int m = 1; m < 4; m <<= 1) {
#pragma unroll
        for (int op = 0; op < 4; op++) {
            mx[op] = max2(mx[op], shfl2(mx[op], m));
            sm[op] = add2(sm[op], shfl2(sm[op], m));
        }
    }

    // ---- transpose pooled h to lane=o via per-warp smem (img area is dead) -
    __syncwarp();
    {
        float2* hb = (float2*)xs;                // [u][o] = (max, sum)
        if (kq == 0) {
#pragma unroll
            for (int op = 0; op < 4; op++) {
                int o = o0 + 2 * op;
                hb[uu * 32 + o]     = make_float2(mx[op].x, sm[op].x);
                hb[uu * 32 + o + 1] = make_float2(mx[op].y, sm[op].y);
            }
        }
    }
    __syncwarp();
    float2 hreg0 = ((float2*)xs)[lane];
    float2 hreg1 = ((float2*)xs)[32 + lane];

    // ---- conv2 for both units: w2c read once per warp, h via shfl ----------
    {
        float2 a0 = make_float2(e2v0, 0.f);
        float2 a1 = make_float2(e2v1, 0.f);
#pragma unroll 8
        for (int i = 0; i < 32; i++) {
            float2 w = s_w2c[i * 32 + lane];
            float2 h0 = make_float2(__shfl_sync(0xffffffffu, hreg0.x, i),
                                    __shfl_sync(0xffffffffu, hreg0.y, i));
            float2 h1 = make_float2(__shfl_sync(0xffffffffu, hreg1.x, i),
                                    __shfl_sync(0xffffffffu, hreg1.y, i));
            a0 = ffma2(w, h0, a0);
            a1 = ffma2(w, h1, a1);
        }
        float* so = s_out + lane * 17 + wrp * 2;
        so[0] = fmaxf(a0.x + a0.y, 0.0f);
        so[1] = fmaxf(a1.x + a1.y, 0.0f);
    }

    // block-wide sync, then coalesced float2 stores (16 n per o row)
    __syncthreads();
    {
        int o = t >> 3, j = (t & 7) * 2;
        float2 v = make_float2(s_out[o * 17 + j], s_out[o * 17 + j + 1]);
        *reinterpret_cast<float2*>(out_b + o * NPTS + n0 + j) = v;
    }
}

// ---------------- launch ----------------------------------------------------
typedef CUresult (*PFN_encodeTiled)(
    CUtensorMap*, CUtensorMapDataType, cuuint32_t, void*,
    const cuuint64_t*, const cuuint64_t*, const cuuint32_t*, const cuuint32_t*,
    CUtensorMapInterleave, CUtensorMapSwizzle, CUtensorMapL2promotion,
    CUtensorMapFloatOOBfill);

extern "C" void kernel_launch(void* const* d_in, const int* in_sizes, int n_in,
                              void* d_out, int out_size)
{
    const float* points = (const float*)d_in[0];
    void*        img    = (void*)d_in[1];
    void*        dist   = (void*)d_in[2];
    const int*   idx    = (const int*)  d_in[3];

    prep_kernel<<<1, 256>>>(
        (const float*)d_in[4],  (const float*)d_in[5],
        (const float*)d_in[6],  (const float*)d_in[7],
        (const float*)d_in[8],  (const float*)d_in[9],
        (const float*)d_in[10], (const float*)d_in[11],
        (const float*)d_in[12], (const float*)d_in[13],
        (const float*)d_in[14], (const float*)d_in[15]);

    // driver entry point via runtime (no -lcuda link needed)
    PFN_encodeTiled encode = nullptr;
    {
        void* fn = nullptr;
#if CUDART_VERSION >= 12000
        cudaDriverEntryPointQueryResult qr;
        cudaGetDriverEntryPoint("cuTensorMapEncodeTiled", &fn, cudaEnableDefault, &qr);
#else
        cudaGetDriverEntryPoint("cuTensorMapEncodeTiled", &fn, cudaEnableDefault);
#endif
        encode = (PFN_encodeTiled)fn;
    }

    CUtensorMap tmap_img{}, tmap_dist{};
    {
        cuuint64_t dims[4]    = {KNN, NPTS, CIMG, 4};
        cuuint64_t strides[3] = {KNN * 4ull,
                                 (cuuint64_t)NPTS * KNN * 4ull,
                                 (cuuint64_t)CIMG * NPTS * KNN * 4ull};
        cuuint32_t box[4]     = {KNN, UPW, CIMG, 1};
        cuuint32_t estr[4]    = {1, 1, 1, 1};
        encode(&tmap_img, CU_TENSOR_MAP_DATA_TYPE_FLOAT32, 4, img,
               dims, strides, box, estr,
               CU_TENSOR_MAP_INTERLEAVE_NONE, CU_TENSOR_MAP_SWIZZLE_NONE,
               CU_TENSOR_MAP_L2_PROMOTION_L2_128B,
               CU_TENSOR_MAP_FLOAT_OOB_FILL_NONE);
    }
    {
        cuuint64_t dims[3]    = {KNN, NPTS, 4};
        cuuint64_t strides[2] = {KNN * 4ull, (cuuint64_t)NPTS * KNN * 4ull};
        cuuint32_t box[3]     = {KNN, UPW, 1};
        cuuint32_t estr[3]    = {1, 1, 1};
        encode(&tmap_dist, CU_TENSOR_MAP_DATA_TYPE_FLOAT32, 3, dist,
               dims, strides, box, estr,
               CU_TENSOR_MAP_INTERLEAVE_NONE, CU_TENSOR_MAP_SWIZZLE_NONE,
               CU_TENSOR_MAP_L2_PROMOTION_L2_128B,
               CU_TENSOR_MAP_FLOAT_OOB_FILL_NONE);
    }

    cudaFuncSetAttribute(pif_main, cudaFuncAttributeMaxDynamicSharedMemorySize,
                         SMEM_BYTES);
    pif_main<<<NBLOCKS, THREADS, SMEM_BYTES>>>(tmap_img, tmap_dist,
                                               points, idx, (float*)d_out);
}

// round 12
// speedup vs baseline: 1.3842x; 1.0542x over previous
#include <cuda_runtime.h>
#include <cuda.h>

#define NPTS 16384
#define KNN  16
#define CIMG 54
#define NCH  58                      // 54 img + dist + nb0..2
#define THREADS 256
#define WARPS 8
#define UPW 4                        // n-units per warp
#define NB (WARPS * UPW)             // 32 units per block
#define NBLOCKS ((4 * NPTS) / NB)    // 2048
#define CCHUNK 18                    // img channels per TMA chunk (3 chunks)

// ---------------- folded-weight scratch (device global; no allocs) ----------
struct Prep {
    float  ws[NCH * 32];     // [row c][o]: conv1 weight, BN-folded
    float2 w2c[32 * 32];     // [i][o2] = (w2_max, w2_mean/16), BN-folded
    float4 wep4[32];         // per o: (wep0, wep1, wep2, bias1_folded)
    float4 w2e4[32];         // per o2: (w2ep0, w2ep1, w2ep2, bias2_folded)
};
__device__ Prep g_prep;

// ---------------- packed fp32x2 helpers -------------------------------------
union F2U { float2 f; unsigned long long u; };
__device__ __forceinline__ float2 ffma2(float2 a, float2 b, float2 c) {
    F2U A, B, C, D;
    A.f = a; B.f = b; C.f = c;
    asm("fma.rn.f32x2 %0, %1, %2, %3;" : "=l"(D.u) : "l"(A.u), "l"(B.u), "l"(C.u));
    return D.f;
}
__device__ __forceinline__ float2 dup2(float w) {
    F2U D;
    asm("mov.b64 %0, {%1, %1};" : "=l"(D.u) : "f"(w));
    return D.f;
}
__device__ __forceinline__ float2 relu2(float2 a) {
    return make_float2(fmaxf(a.x, 0.f), fmaxf(a.y, 0.f));
}
__device__ __forceinline__ float2 max2(float2 a, float2 b) {
    return make_float2(fmaxf(a.x, b.x), fmaxf(a.y, b.y));
}
__device__ __forceinline__ float2 add2(float2 a, float2 b) {
    return make_float2(a.x + b.x, a.y + b.y);
}

// ---------------- prep: fold BN + concat algebra into weights ---------------
__global__ void prep_kernel(
    const float* __restrict__ w1, const float* __restrict__ b1,
    const float* __restrict__ g1, const float* __restrict__ be1,
    const float* __restrict__ m1, const float* __restrict__ v1,
    const float* __restrict__ w2, const float* __restrict__ b2,
    const float* __restrict__ g2, const float* __restrict__ be2,
    const float* __restrict__ m2, const float* __restrict__ v2)
{
    __shared__ float s1[32], s2[32], bf1[32], bf2[32];
    int t = threadIdx.x;
    if (t < 32) {
        float sc = g1[t] / sqrtf(v1[t] + 1e-6f);
        s1[t]  = sc;
        bf1[t] = (b1[t] - m1[t]) * sc + be1[t];
        float sc2 = g2[t] / sqrtf(v2[t] + 1e-6f);
        s2[t]  = sc2;
        bf2[t] = (b2[t] - m2[t]) * sc2 + be2[t];
    }
    __syncthreads();

    // conv1 rows: 0..53 img (w1 col 10+c), 54 dist (col 9), 55..57 nb (col 3+c - col 6+c)
    for (int i = t; i < NCH * 32; i += blockDim.x) {
        int c = i >> 5, o = i & 31;
        float wv;
        if (c < 54)       wv = w1[o * 64 + 10 + c];
        else if (c == 54) wv = w1[o * 64 + 9];
        else              wv = w1[o * 64 + 3 + (c - 55)] - w1[o * 64 + 6 + (c - 55)];
        g_prep.ws[i] = wv * s1[o];
    }
    for (int i = t; i < 32 * 32; i += blockDim.x) {
        int c = i >> 5, o = i & 31;
        float wm = w2[o * 70 + c] * s2[o];
        float wsn = w2[o * 70 + 35 + c] * s2[o] * 0.0625f;
        g_prep.w2c[i] = make_float2(wm, wsn);
    }
    if (t < 32) {
        int o = t;
        g_prep.wep4[o] = make_float4(
            (w1[o * 64 + 0] + w1[o * 64 + 6]) * s1[o],
            (w1[o * 64 + 1] + w1[o * 64 + 7]) * s1[o],
            (w1[o * 64 + 2] + w1[o * 64 + 8]) * s1[o],
            bf1[o]);
        g_prep.w2e4[o] = make_float4(
            (w2[o * 70 + 32] + w2[o * 70 + 67]) * s2[o],
            (w2[o * 70 + 33] + w2[o * 70 + 68]) * s2[o],
            (w2[o * 70 + 34] + w2[o * 70 + 69]) * s2[o],
            bf2[o]);
    }
}

// ---------------- dynamic smem layout (floats) ------------------------------
// per-warp region xs (WSTRIDE floats; WSTRIDE*4 MUST be a multiple of 128 for
// TMA destination alignment — 2592*4 = 10368 = 81*128):
//   BUF0 [0,1152)     img chunk buffer A: [18 ch][4 units][16 k]
//   BUF1 [1152,2304)  img chunk buffer B
//   DISTO[2304,2368)  dist: [4 units][16]
//   NBO  [2368,2560)  nb:   [4 units][3 rows][16]
//   EPO  [2560,2576)  ep:   [4 units][3] (+pad)
//   [2576,2592)       pad to 128B multiple
//   (BUF0 reused after conv1 for the pooled-h transpose)
#define BUF0  0
#define BUF1  1152
#define DISTO 2304
#define NBO   2368
#define EPO   2560
#define WSTRIDE 2592
#define W1_OFF   (WARPS * WSTRIDE)            // 20736
#define W2C_OFF  (W1_OFF + NCH * 32)          // 22592
#define WEP_OFF  (W2C_OFF + 2048)             // 24640
#define W2E_OFF  (WEP_OFF + 128)              // 24768
#define OUT_OFF  (W2E_OFF + 128)              // 24896  (32 o x 33)
#define MBAR_OFF (OUT_OFF + 1056)             // 25952  (8 warps x 2 mbar)
#define SMEM_FLOATS (MBAR_OFF + 32)           // 25984
#define SMEM_BYTES  (SMEM_FLOATS * 4)         // 103936

#define CH_BYTES   (CCHUNK * UPW * KNN * 4)   // 4608
#define DIST_BYTES (UPW * KNN * 4)            // 256

#define MBWAIT(MB, PH)                                                         \
    {                                                                          \
        unsigned done_;                                                        \
        asm volatile(                                                          \
            "{\n\t"                                                            \
            ".reg .pred p;\n\t"                                                \
            "mbarrier.try_wait.parity.acquire.cta.shared::cta.b64 p, [%1], %2;\n\t" \
            "selp.b32 %0, 1, 0, p;\n\t"                                        \
            "}"                                                                \
            : "=r"(done_) : "r"(MB), "r"((unsigned)(PH)) : "memory");          \
        if (!done_) {                                                          \
            asm volatile(                                                      \
                "{\n\t"                                                        \
                ".reg .pred P1;\n\t"                                           \
                "WL_%=:\n\t"                                                   \
                "mbarrier.try_wait.parity.acquire.cta.shared::cta.b64 P1, [%0], %1, 0x989680;\n\t" \
                "@P1 bra.uni WD_%=;\n\t"                                       \
                "bra.uni WL_%=;\n\t"                                           \
                "WD_%=:\n\t"                                                   \
                "}"                                                            \
                :: "r"(MB), "r"((unsigned)(PH)) : "memory");                   \
        }                                                                      \
    }

__global__ __launch_bounds__(THREADS, 2) void pif_main(
    const __grid_constant__ CUtensorMap tmap_img,
    const __grid_constant__ CUtensorMap tmap_dist,
    const float* __restrict__ points, const int* __restrict__ idx,
    float* __restrict__ out)
{
    extern __shared__ float smem[];
    float*  s_w1  = smem + W1_OFF;
    float2* s_w2c = (float2*)(smem + W2C_OFF);
    float4* s_wep = (float4*)(smem + WEP_OFF);
    float4* s_w2e = (float4*)(smem + W2E_OFF);
    float*  s_out = smem + OUT_OFF;

    const int t    = threadIdx.x;
    const int lane = t & 31, wrp = t >> 5;
    const int og = lane >> 3;                 // o-group (8 outputs)
    const int j  = lane & 7;                  // (unit, k-half)
    const int uu = j >> 1;                    // unit 0..3
    const int kh = j & 1;                     // k-octet 0..1
    const int o0 = og * 8;

    const int b  = blockIdx.x >> 9;           // 512 blocks per batch
    const int n0 = (blockIdx.x & 511) * NB;
    const int nw = n0 + wrp * UPW;            // this warp's first unit

    float* xs = smem + wrp * WSTRIDE;
    const unsigned mb0 = (unsigned)__cvta_generic_to_shared(smem + MBAR_OFF + wrp * 4);
    const unsigned mb1 = mb0 + 8;

    // ---- mbarrier init + kick off chunk0(+dist) and chunk1 TMA -------------
    if (lane == 0) {
        asm volatile("mbarrier.init.shared.b64 [%0], 1;" :: "r"(mb0) : "memory");
        asm volatile("mbarrier.init.shared.b64 [%0], 1;" :: "r"(mb1) : "memory");
    }
    __syncwarp();
    asm volatile("fence.proxy.async.shared::cta;" ::: "memory");
    if (lane == 0) {
        asm volatile("mbarrier.arrive.expect_tx.shared.b64 _, [%0], %1;"
                     :: "r"(mb0), "r"((unsigned)(CH_BYTES + DIST_BYTES)) : "memory");
        unsigned d0 = (unsigned)__cvta_generic_to_shared(xs + BUF0);
        asm volatile(
            "cp.async.bulk.tensor.4d.shared::cta.global.tile.mbarrier::complete_tx::bytes "
            "[%0], [%1, {%2, %3, %4, %5}], [%6];"
            :: "r"(d0), "l"(&tmap_img),
               "r"(0), "r"(nw), "r"(0), "r"(b), "r"(mb0) : "memory");
        unsigned dd = (unsigned)__cvta_generic_to_shared(xs + DISTO);
        asm volatile(
            "cp.async.bulk.tensor.3d.shared::cta.global.tile.mbarrier::complete_tx::bytes "
            "[%0], [%1, {%2, %3, %4}], [%5];"
            :: "r"(dd), "l"(&tmap_dist),
               "r"(0), "r"(nw), "r"(b), "r"(mb0) : "memory");
        asm volatile("mbarrier.arrive.expect_tx.shared.b64 _, [%0], %1;"
                     :: "r"(mb1), "r"((unsigned)CH_BYTES) : "memory");
        unsigned d1 = (unsigned)__cvta_generic_to_shared(xs + BUF1);
        asm volatile(
            "cp.async.bulk.tensor.4d.shared::cta.global.tile.mbarrier::complete_tx::bytes "
            "[%0], [%1, {%2, %3, %4, %5}], [%6];"
            :: "r"(d1), "l"(&tmap_img),
               "r"(0), "r"(nw), "r"(CCHUNK), "r"(b), "r"(mb1) : "memory");
    }

    // ---- while TMA flies: weights to smem, nb gather, ep stage -------------
    {
        const float4* src = (const float4*)&g_prep;
        float4* dst = (float4*)(smem + W1_OFF);
        for (int i = t; i < 1040; i += THREADS) dst[i] = src[i];   // ws|w2c|wep|w2e
    }
    const float* pts_b = points + b * (NPTS * 3);
    const int*   idx_b = idx    + b * (NPTS * KNN);
    float*       out_b = out    + b * (32 * NPTS);

    // nb gather: 64 neighbors per warp, 2 per lane
#pragma unroll
    for (int q = 0; q < 2; q++) {
        int qi = lane + q * 32;                // (u, k)
        int u = qi >> 4, k = qi & 15;
        int jn = idx_b[(nw + u) * KNN + k];
        float p0 = pts_b[jn * 3 + 0];
        float p1 = pts_b[jn * 3 + 1];
        float p2 = pts_b[jn * 3 + 2];
        float* r = xs + NBO + u * 48 + k;
        r[0]  = p0;
        r[16] = p1;
        r[32] = p2;
    }
    // ep stage: lanes 0..11 store ep[u][comp]
    if (lane < 12) {
        int u = lane / 3, comp = lane - u * 3;
        xs[EPO + lane] = pts_b[(nw + u) * 3 + comp];
    }

    __syncthreads();                 // weight tables + nb/ep visible

    // ---- conv1 accumulator init: ep-term for this lane's unit --------------
    const float e0 = xs[EPO + uu * 3 + 0];
    const float e1 = xs[EPO + uu * 3 + 1];
    const float e2 = xs[EPO + uu * 3 + 2];
    float2 acc[32];                  // acc[f*4+op]: k = kh*8+f, o = o0+2op(+1)
#pragma unroll
    for (int op = 0; op < 4; op++) {
        float4 wa = s_wep[o0 + 2 * op];
        float4 wb = s_wep[o0 + 2 * op + 1];
        float2 ei = make_float2(
            fmaf(wa.x, e0, fmaf(wa.y, e1, fmaf(wa.z, e2, wa.w))),
            fmaf(wb.x, e0, fmaf(wb.y, e1, fmaf(wb.z, e2, wb.w))));
#pragma unroll
        for (int f = 0; f < 8; f++) acc[f * 4 + op] = ei;
    }

#define ROW(XBASE, C)                                                          \
    {                                                                          \
        const float4 wv0 = *(const float4*)(s_w1 + (C) * 32 + o0);             \
        const float4 wv1 = *(const float4*)(s_w1 + (C) * 32 + o0 + 4);         \
        const float2 wp0 = make_float2(wv0.x, wv0.y);                          \
        const float2 wp1 = make_float2(wv0.z, wv0.w);                          \
        const float2 wp2 = make_float2(wv1.x, wv1.y);                          \
        const float2 wp3 = make_float2(wv1.z, wv1.w);                          \
        const float4 xa = *(const float4*)(XBASE);                             \
        const float4 xb = *(const float4*)((XBASE) + 4);                       \
        float2 xd;                                                             \
        xd = dup2(xa.x);                                                       \
        acc[0]  = ffma2(wp0, xd, acc[0]);  acc[1]  = ffma2(wp1, xd, acc[1]);   \
        acc[2]  = ffma2(wp2, xd, acc[2]);  acc[3]  = ffma2(wp3, xd, acc[3]);   \
        xd = dup2(xa.y);                                                       \
        acc[4]  = ffma2(wp0, xd, acc[4]);  acc[5]  = ffma2(wp1, xd, acc[5]);   \
        acc[6]  = ffma2(wp2, xd, acc[6]);  acc[7]  = ffma2(wp3, xd, acc[7]);   \
        xd = dup2(xa.z);                                                       \
        acc[8]  = ffma2(wp0, xd, acc[8]);  acc[9]  = ffma2(wp1, xd, acc[9]);   \
        acc[10] = ffma2(wp2, xd, acc[10]); acc[11] = ffma2(wp3, xd, acc[11]);  \
        xd = dup2(xa.w);                                                       \
        acc[12] = ffma2(wp0, xd, acc[12]); acc[13] = ffma2(wp1, xd, acc[13]);  \
        acc[14] = ffma2(wp2, xd, acc[14]); acc[15] = ffma2(wp3, xd, acc[15]);  \
        xd = dup2(xb.x);                                                       \
        acc[16] = ffma2(wp0, xd, acc[16]); acc[17] = ffma2(wp1, xd, acc[17]);  \
        acc[18] = ffma2(wp2, xd, acc[18]); acc[19] = ffma2(wp3, xd, acc[19]);  \
        xd = dup2(xb.y);                                                       \
        acc[20] = ffma2(wp0, xd, acc[20]); acc[21] = ffma2(wp1, xd, acc[21]);  \
        acc[22] = ffma2(wp2, xd, acc[22]); acc[23] = ffma2(wp3, xd, acc[23]);  \
        xd = dup2(xb.z);                                                       \
        acc[24] = ffma2(wp0, xd, acc[24]); acc[25] = ffma2(wp1, xd, acc[25]);  \
        acc[26] = ffma2(wp2, xd, acc[26]); acc[27] = ffma2(wp3, xd, acc[27]);  \
        xd = dup2(xb.w);                                                       \
        acc[28] = ffma2(wp0, xd, acc[28]); acc[29] = ffma2(wp1, xd, acc[29]);  \
        acc[30] = ffma2(wp2, xd, acc[30]); acc[31] = ffma2(wp3, xd, acc[31]);  \
    }

    const int xoff = uu * 16 + kh * 8;        // float offset within a row

    // ---- chunk 0: rows 0..17 ----------------------------------------------
    MBWAIT(mb0, 0)
    {
        const float* xc = xs + BUF0 + xoff;
#pragma unroll
        for (int c = 0; c < CCHUNK; c++) ROW(xc + c * 64, c)
    }
    __syncwarp();                             // buf0 consumed by whole warp
    if (lane == 0) {                          // reload buf0 with chunk 2
        asm volatile("mbarrier.arrive.expect_tx.shared.b64 _, [%0], %1;"
                     :: "r"(mb0), "r"((unsigned)CH_BYTES) : "memory");
        unsigned d0 = (unsigned)__cvta_generic_to_shared(xs + BUF0);
        asm volatile(
            "cp.async.bulk.tensor.4d.shared::cta.global.tile.mbarrier::complete_tx::bytes "
            "[%0], [%1, {%2, %3, %4, %5}], [%6];"
            :: "r"(d0), "l"(&tmap_img),
               "r"(0), "r"(nw), "r"(2 * CCHUNK), "r"(b), "r"(mb0) : "memory");
    }

    // ---- chunk 1: rows 18..35 ---------------------------------------------
    MBWAIT(mb1, 0)
    {
        const float* xc = xs + BUF1 + xoff;
#pragma unroll
        for (int c = 0; c < CCHUNK; c++) ROW(xc + c * 64, CCHUNK + c)
    }

    // ---- chunk 2: rows 36..53, then dist + nb ------------------------------
    MBWAIT(mb0, 1)
    {
        const float* xc = xs + BUF0 + xoff;
#pragma unroll
        for (int c = 0; c < CCHUNK; c++) ROW(xc + c * 64, 2 * CCHUNK + c)
    }
    ROW(xs + DISTO + xoff, 54)
    {
        const float* nbb = xs + NBO + uu * 48 + kh * 8;
        ROW(nbb + 0,  55)
        ROW(nbb + 16, 56)
        ROW(nbb + 32, 57)
    }
#undef ROW

    // ---- ReLU + pool: in-lane over 8 k, 1 shfl round over kh ---------------
    float2 mx[4], sm[4];
#pragma unroll
    for (int op = 0; op < 4; op++) {
        float2 m = relu2(acc[op]);
        float2 s = m;
#pragma unroll
        for (int f = 1; f < 8; f++) {
            float2 a = relu2(acc[f * 4 + op]);
            m = max2(m, a);
            s = add2(s, a);
        }
        mx[op] = make_float2(fmaxf(m.x, __shfl_xor_sync(0xffffffffu, m.x, 1)),
                             fmaxf(m.y, __shfl_xor_sync(0xffffffffu, m.y, 1)));
        sm[op] = make_float2(s.x + __shfl_xor_sync(0xffffffffu, s.x, 1),
                             s.y + __shfl_xor_sync(0xffffffffu, s.y, 1));
    }

    // ---- transpose pooled h to lane=o via per-warp smem (buf0 is dead) -----
    __syncwarp();
    {
        float2* hb = (float2*)(xs + BUF0);    // [u][o] = (max, sum)
        if (kh == 0) {
#pragma unroll
            for (int op = 0; op < 4; op++) {
                int o = o0 + 2 * op;
                hb[uu * 32 + o]     = make_float2(mx[op].x, sm[op].x);
                hb[uu * 32 + o + 1] = make_float2(mx[op].y, sm[op].y);
            }
        }
    }
    __syncwarp();
    float2 h0 = ((float2*)(xs + BUF0))[lane];
    float2 h1 = ((float2*)(xs + BUF0))[32 + lane];
    float2 h2 = ((float2*)(xs + BUF0))[64 + lane];
    float2 h3 = ((float2*)(xs + BUF0))[96 + lane];

    // ---- conv2 for 4 units: w2c read once per warp, h via shfl -------------
    {
        const float4 w2e = s_w2e[lane];
        float2 a0, a1, a2, a3;
        {
            float q0 = xs[EPO + 0], q1 = xs[EPO + 1],  q2 = xs[EPO + 2];
            a0 = make_float2(fmaf(w2e.x, q0, fmaf(w2e.y, q1, fmaf(w2e.z, q2, w2e.w))), 0.f);
            q0 = xs[EPO + 3]; q1 = xs[EPO + 4]; q2 = xs[EPO + 5];
            a1 = make_float2(fmaf(w2e.x, q0, fmaf(w2e.y, q1, fmaf(w2e.z, q2, w2e.w))), 0.f);
            q0 = xs[EPO + 6]; q1 = xs[EPO + 7]; q2 = xs[EPO + 8];
            a2 = make_float2(fmaf(w2e.x, q0, fmaf(w2e.y, q1, fmaf(w2e.z, q2, w2e.w))), 0.f);
            q0 = xs[EPO + 9]; q1 = xs[EPO + 10]; q2 = xs[EPO + 11];
            a3 = make_float2(fmaf(w2e.x, q0, fmaf(w2e.y, q1, fmaf(w2e.z, q2, w2e.w))), 0.f);
        }
#pragma unroll 8
        for (int i = 0; i < 32; i++) {
            float2 w = s_w2c[i * 32 + lane];
            float2 g0 = make_float2(__shfl_sync(0xffffffffu, h0.x, i),
                                    __shfl_sync(0xffffffffu, h0.y, i));
            float2 g1 = make_float2(__shfl_sync(0xffffffffu, h1.x, i),
                                    __shfl_sync(0xffffffffu, h1.y, i));
            float2 g2 = make_float2(__shfl_sync(0xffffffffu, h2.x, i),
                                    __shfl_sync(0xffffffffu, h2.y, i));
            float2 g3 = make_float2(__shfl_sync(0xffffffffu, h3.x, i),
                                    __shfl_sync(0xffffffffu, h3.y, i));
            a0 = ffma2(w, g0, a0);
            a1 = ffma2(w, g1, a1);
            a2 = ffma2(w, g2, a2);
            a3 = ffma2(w, g3, a3);
        }
        float* so = s_out + lane * 33 + wrp * 4;
        so[0] = fmaxf(a0.x + a0.y, 0.0f);
        so[1] = fmaxf(a1.x + a1.y, 0.0f);
        so[2] = fmaxf(a2.x + a2.y, 0.0f);
        so[3] = fmaxf(a3.x + a3.y, 0.0f);
    }

    // block-wide sync, then coalesced float4 stores (32 n per o row)
    __syncthreads();
    {
        int o = t >> 3, j4 = (t & 7) * 4;
        float4 v = make_float4(s_out[o * 33 + j4],     s_out[o * 33 + j4 + 1],
                               s_out[o * 33 + j4 + 2], s_out[o * 33 + j4 + 3]);
        *reinterpret_cast<float4*>(out_b + o * NPTS + n0 + j4) = v;
    }
}

// ---------------- launch ----------------------------------------------------
typedef CUresult (*PFN_encodeTiled)(
    CUtensorMap*, CUtensorMapDataType, cuuint32_t, void*,
    const cuuint64_t*, const cuuint64_t*, const cuuint32_t*, const cuuint32_t*,
    CUtensorMapInterleave, CUtensorMapSwizzle, CUtensorMapL2promotion,
    CUtensorMapFloatOOBfill);

extern "C" void kernel_launch(void* const* d_in, const int* in_sizes, int n_in,
                              void* d_out, int out_size)
{
    const float* points = (const float*)d_in[0];
    void*        img    = (void*)d_in[1];
    void*        dist   = (void*)d_in[2];
    const int*   idx    = (const int*)  d_in[3];

    prep_kernel<<<1, 256>>>(
        (const float*)d_in[4],  (const float*)d_in[5],
        (const float*)d_in[6],  (const float*)d_in[7],
        (const float*)d_in[8],  (const float*)d_in[9],
        (const float*)d_in[10], (const float*)d_in[11],
        (const float*)d_in[12], (const float*)d_in[13],
        (const float*)d_in[14], (const float*)d_in[15]);

    // driver entry point via runtime (no -lcuda link needed)
    PFN_encodeTiled encode = nullptr;
    {
        void* fn = nullptr;
#if CUDART_VERSION >= 12000
        cudaDriverEntryPointQueryResult qr;
        cudaGetDriverEntryPoint("cuTensorMapEncodeTiled", &fn, cudaEnableDefault, &qr);
#else
        cudaGetDriverEntryPoint("cuTensorMapEncodeTiled", &fn, cudaEnableDefault);
#endif
        encode = (PFN_encodeTiled)fn;
    }

    CUtensorMap tmap_img{}, tmap_dist{};
    {
        cuuint64_t dims[4]    = {KNN, NPTS, CIMG, 4};
        cuuint64_t strides[3] = {KNN * 4ull,
                                 (cuuint64_t)NPTS * KNN * 4ull,
                                 (cuuint64_t)CIMG * NPTS * KNN * 4ull};
        cuuint32_t box[4]     = {KNN, UPW, CCHUNK, 1};
        cuuint32_t estr[4]    = {1, 1, 1, 1};
        encode(&tmap_img, CU_TENSOR_MAP_DATA_TYPE_FLOAT32, 4, img,
               dims, strides, box, estr,
               CU_TENSOR_MAP_INTERLEAVE_NONE, CU_TENSOR_MAP_SWIZZLE_NONE,
               CU_TENSOR_MAP_L2_PROMOTION_L2_128B,
               CU_TENSOR_MAP_FLOAT_OOB_FILL_NONE);
    }
    {
        cuuint64_t dims[3]    = {KNN, NPTS, 4};
        cuuint64_t strides[2] = {KNN * 4ull, (cuuint64_t)NPTS * KNN * 4ull};
        cuuint32_t box[3]     = {KNN, UPW, 1};
        cuuint32_t estr[3]    = {1, 1, 1};
        encode(&tmap_dist, CU_TENSOR_MAP_DATA_TYPE_FLOAT32, 3, dist,
               dims, strides, box, estr,
               CU_TENSOR_MAP_INTERLEAVE_NONE, CU_TENSOR_MAP_SWIZZLE_NONE,
               CU_TENSOR_MAP_L2_PROMOTION_L2_128B,
               CU_TENSOR_MAP_FLOAT_OOB_FILL_NONE);
    }

    cudaFuncSetAttribute(pif_main, cudaFuncAttributeMaxDynamicSharedMemorySize,
                         SMEM_BYTES);
    pif_main<<<NBLOCKS, THREADS, SMEM_BYTES>>>(tmap_img, tmap_dist,
                                               points, idx, (float*)d_out);
}